// round 8
// baseline (speedup 1.0000x reference)
#include <cuda_runtime.h>
#include <cuda_bf16.h>
#include <math.h>
#include <stdint.h>

// Problem constants
#define B_ 64
#define S_ 100
#define D_ 1024
#define H_ 16
#define F_ 4096
#define DEPTH_ 64
#define BS_ (B_ * S_)          // 6400
#define N_QKV 3072
#define EPS_ 1e-6f

// ---------------------------------------------------------------------------
// Scratch (device globals; no allocations allowed)
// ---------------------------------------------------------------------------
__device__ float g_pe[S_ * D_];
__device__ float g_x[BS_ * D_];      // full fp32 (residual path)
__device__ float g_xr[BS_ * D_];     // tf32-rounded (GEMM A operand)
__device__ float g_Wqkv[D_ * N_QKV]; // rounded, [K,N]
__device__ float g_bqkv[N_QKV];
__device__ float g_Wor[D_ * D_];     // rounded Wo [K,N]
__device__ float g_W1r[D_ * F_];     // rounded W1 [K,N]
__device__ float g_W2r[F_ * D_];     // rounded W2 [K,N]
__device__ float g_QKV[BS_ * N_QKV];
__device__ float g_ctx[BS_ * D_];    // rounded at attention epilogue
__device__ float g_t1[2 * BS_ * D_]; // split-K partial buffers
__device__ float g_x1[BS_ * D_];
__device__ float g_x1r[BS_ * D_];
__device__ float g_ffh[BS_ * F_];    // rounded at relu epilogue

__device__ __forceinline__ uint32_t f2tf32(float x) {
    uint32_t r;
    asm("cvt.rna.tf32.f32 %0, %1;" : "=r"(r) : "f"(x));
    return r;
}
__device__ __forceinline__ float roundtf(float x) {
    return __uint_as_float(f2tf32(x));
}

__device__ __forceinline__ void mma_tf32(float* d, const uint32_t* a, const uint32_t* b) {
    asm volatile(
        "mma.sync.aligned.m16n8k8.row.col.f32.tf32.tf32.f32 "
        "{%0,%1,%2,%3}, {%4,%5,%6,%7}, {%8,%9}, {%0,%1,%2,%3};\n"
        : "+f"(d[0]), "+f"(d[1]), "+f"(d[2]), "+f"(d[3])
        : "r"(a[0]), "r"(a[1]), "r"(a[2]), "r"(a[3]), "r"(b[0]), "r"(b[1]));
}

// ---------------------------------------------------------------------------
// Positional encoding (fp64 to match numpy float64 table)
// ---------------------------------------------------------------------------
__global__ void pe_kernel(float* __restrict__ pe) {
    int idx = blockIdx.x * blockDim.x + threadIdx.x;
    if (idx >= S_ * D_) return;
    int s = idx / D_;
    int d = idx % D_;
    int k2 = d & ~1;
    double div = pow(10000.0, (double)k2 / (double)D_);
    double arg = (double)s / div;
    pe[idx] = (float)((d & 1) ? cos(arg) : sin(arg));
}

// ---------------------------------------------------------------------------
// Embedding gather + positional add; writes fp32 x and tf32-rounded xr
// ---------------------------------------------------------------------------
__global__ void embed_kernel(const int* __restrict__ tokens,
                             const float* __restrict__ emb,
                             const float* __restrict__ pe,
                             float* __restrict__ x, float* __restrict__ xr) {
    int idx = blockIdx.x * blockDim.x + threadIdx.x;
    if (idx >= BS_ * D_ / 4) return;
    int row = idx / (D_ / 4);
    int c4 = idx % (D_ / 4);
    int tok = tokens[row];
    float4 e = ((const float4*)(emb + (size_t)tok * D_))[c4];
    float4 p = ((const float4*)(pe + (size_t)(row % S_) * D_))[c4];
    float4 o;
    o.x = e.x + p.x; o.y = e.y + p.y; o.z = e.z + p.z; o.w = e.w + p.w;
    ((float4*)x)[idx] = o;
    float4 r;
    r.x = roundtf(o.x); r.y = roundtf(o.y); r.z = roundtf(o.z); r.w = roundtf(o.w);
    ((float4*)xr)[idx] = r;
}

// ---------------------------------------------------------------------------
// Permute Wq/Wk/Wv [H,D,64] -> combined [D, 3072] (rounded); biases -> [3072]
// ---------------------------------------------------------------------------
__global__ void permute_qkv_kernel(const float* __restrict__ Wq, const float* __restrict__ Wk,
                                   const float* __restrict__ Wv,
                                   const float* __restrict__ bq, const float* __restrict__ bk,
                                   const float* __restrict__ bv,
                                   float* __restrict__ Wout, float* __restrict__ bout) {
    int idx = blockIdx.x * blockDim.x + threadIdx.x;
    const int total = 3 * D_ * D_;
    if (idx < total) {
        int which = idx / (D_ * D_);
        int r = idx % (D_ * D_);
        int d = r / D_;
        int n = r % D_;
        int h = n >> 6, e = n & 63;
        const float* W = (which == 0) ? Wq : ((which == 1) ? Wk : Wv);
        Wout[(size_t)d * N_QKV + which * D_ + n] =
            roundtf(W[((size_t)h * D_ + d) * DEPTH_ + e]);
    }
    if (idx < N_QKV) {
        int which = idx / D_;
        int n = idx % D_;
        const float* bb = (which == 0) ? bq : ((which == 1) ? bk : bv);
        bout[idx] = bb[n];
    }
}

// ---------------------------------------------------------------------------
// Combined tf32 round-copy of Wo, W1, W2 in one launch.
// ---------------------------------------------------------------------------
#define N4_WO (D_ * D_ / 4)
#define N4_W1 (D_ * F_ / 4)
#define N4_W2 (F_ * D_ / 4)
__global__ void roundcpy3_kernel(const float* __restrict__ Wo, float* __restrict__ WoR,
                                 const float* __restrict__ W1, float* __restrict__ W1R,
                                 const float* __restrict__ W2, float* __restrict__ W2R) {
    int idx = blockIdx.x * blockDim.x + threadIdx.x;
    const float* in;
    float* out;
    int off;
    if (idx < N4_WO) { in = Wo; out = WoR; off = idx; }
    else if (idx < N4_WO + N4_W1) { in = W1; out = W1R; off = idx - N4_WO; }
    else if (idx < N4_WO + N4_W1 + N4_W2) { in = W2; out = W2R; off = idx - N4_WO - N4_W1; }
    else return;
    float4 v = ((const float4*)in)[off];
    float4 r;
    r.x = roundtf(v.x); r.y = roundtf(v.y); r.z = roundtf(v.z); r.w = roundtf(v.w);
    ((float4*)out)[off] = r;
}

// ---------------------------------------------------------------------------
// TF32 mma.sync GEMM. 128x128 CTA tile, 4 warps of 64x64, k-step 16,
// 4-stage cp.async pipeline (3 tiles in flight). Split-K via gridDim.z:
// each z computes K/gridDim.z, writes raw partial to C + z*M*N (EPI=0).
// EPI: bit0 bias, bit1 relu, bit2 residual, bit3 round-output.
// ---------------------------------------------------------------------------
#define ASTRIDE 20                      // 16 cols + 4 pad; banks 20g+tg all distinct
#define BSTRIDE 136                     // banks 8tg+g all distinct
#define AFLOATS (128 * ASTRIDE)         // 2560
#define BFLOATS (16 * BSTRIDE)          // 2176
#define STAGEF  (AFLOATS + BFLOATS)     // 4736
#define NSTAGE 4
#define SMEM_GEMM (NSTAGE * STAGEF * 4) // 75776

template <int EPI>
__global__ __launch_bounds__(128, 2)
void mma_gemm(const float* __restrict__ A, const float* __restrict__ Bm,
              float* __restrict__ C, const float* __restrict__ bias,
              const float* __restrict__ res, int M, int N, int K) {
    extern __shared__ float smf[];
    int tid = threadIdx.x;
    int lane = tid & 31, warp = tid >> 5;
    int wm = warp & 1, wn = warp >> 1;
    int g = lane >> 2, tg = lane & 3;
    int bm = blockIdx.y * 128, bn = blockIdx.x * 128;

    // Split-K offsets
    int kspl = K / gridDim.z;
    int kOff = blockIdx.z * kspl;
    A += kOff;
    Bm += (size_t)kOff * N;
    C += (size_t)blockIdx.z * M * N;

    uint32_t smemBase = (uint32_t)__cvta_generic_to_shared(smf);

    float acc[4][8][4];
#pragma unroll
    for (int i = 0; i < 4; i++)
#pragma unroll
        for (int j = 0; j < 8; j++)
#pragma unroll
            for (int c = 0; c < 4; c++) acc[i][j][c] = 0.f;

    const int KT = kspl / 16;

    // Prefetch geometry (128 threads), one 16B chunk per (thread, q):
    // A tile 128x16: row = q*32 + (tid>>2), colv = tid&3
    // B tile 16x128: krow = q*4 + (tid>>5), colv = tid&31
    const float* aSrc = A + (size_t)(bm + (tid >> 2)) * K + (tid & 3) * 4;
    const float* bSrc = Bm + (size_t)(tid >> 5) * N + bn + (tid & 31) * 4;
    uint32_t aDst0 = smemBase + (uint32_t)(((tid >> 2) * ASTRIDE + (tid & 3) * 4)) * 4;
    uint32_t bDst0 = smemBase + AFLOATS * 4 + (uint32_t)(((tid >> 5) * BSTRIDE + (tid & 31) * 4)) * 4;

    auto prefetch = [&](int stage) {
        uint32_t so = (uint32_t)(stage * STAGEF * 4);
#pragma unroll
        for (int q = 0; q < 4; q++) {
            uint32_t dst = aDst0 + so + (uint32_t)(q * 32 * ASTRIDE) * 4;
            const float* src = aSrc + (size_t)(q * 32) * K;
            asm volatile("cp.async.cg.shared.global [%0], [%1], 16;" :: "r"(dst), "l"(src));
        }
#pragma unroll
        for (int q = 0; q < 4; q++) {
            uint32_t dst = bDst0 + so + (uint32_t)(q * 4 * BSTRIDE) * 4;
            const float* src = bSrc + (size_t)(q * 4) * N;
            asm volatile("cp.async.cg.shared.global [%0], [%1], 16;" :: "r"(dst), "l"(src));
        }
        aSrc += 16;
        bSrc += (size_t)16 * N;
        asm volatile("cp.async.commit_group;");
    };

    // Prologue: 3 tiles in flight.
    prefetch(0);
    prefetch(1);
    prefetch(2);

    for (int kt = 0; kt < KT; kt++) {
        asm volatile("cp.async.wait_group 2;");
        __syncthreads();

        const uint32_t* As = (const uint32_t*)(smf + (kt & 3) * STAGEF);
        const uint32_t* Bs = As + AFLOATS;
#pragma unroll
        for (int ks = 0; ks < 2; ks++) {
            int k0 = ks * 8;
            uint32_t afr[4][4];
#pragma unroll
            for (int mi = 0; mi < 4; mi++) {
                int m = wm * 64 + mi * 16 + g;
                afr[mi][0] = As[m * ASTRIDE + k0 + tg];
                afr[mi][1] = As[(m + 8) * ASTRIDE + k0 + tg];
                afr[mi][2] = As[m * ASTRIDE + k0 + tg + 4];
                afr[mi][3] = As[(m + 8) * ASTRIDE + k0 + tg + 4];
            }
            uint32_t bfr[8][2];
#pragma unroll
            for (int ni = 0; ni < 8; ni++) {
                int n = wn * 64 + ni * 8 + g;
                bfr[ni][0] = Bs[(k0 + tg) * BSTRIDE + n];
                bfr[ni][1] = Bs[(k0 + tg + 4) * BSTRIDE + n];
            }
#pragma unroll
            for (int mi = 0; mi < 4; mi++)
#pragma unroll
                for (int ni = 0; ni < 8; ni++)
                    mma_tf32(acc[mi][ni], afr[mi], bfr[ni]);
        }
        __syncthreads();

        if (kt + 3 < KT) prefetch((kt + 3) & 3);
        else asm volatile("cp.async.commit_group;");   // keep group count aligned
    }

#pragma unroll
    for (int mi = 0; mi < 4; mi++) {
#pragma unroll
        for (int rr = 0; rr < 2; rr++) {
            int row = bm + wm * 64 + mi * 16 + rr * 8 + g;
#pragma unroll
            for (int ni = 0; ni < 8; ni++) {
                int col = bn + wn * 64 + ni * 8 + tg * 2;
                float vx = acc[mi][ni][rr * 2 + 0];
                float vy = acc[mi][ni][rr * 2 + 1];
                if (EPI & 1) { vx += bias[col]; vy += bias[col + 1]; }
                if (EPI & 4) {
                    const float* rp = res + (size_t)row * N + col;
                    vx += rp[0]; vy += rp[1];
                }
                if (EPI & 2) { vx = fmaxf(vx, 0.f); vy = fmaxf(vy, 0.f); }
                if (EPI & 8) { vx = roundtf(vx); vy = roundtf(vy); }
                *(float2*)&C[(size_t)row * N + col] = make_float2(vx, vy);
            }
        }
    }
}

// ---------------------------------------------------------------------------
// Fused attention per (b, h) — tensor-core QK^T and AV via mma.sync tf32.
// ---------------------------------------------------------------------------
#define QS_STR 76
#define KT_STR 104
#define VS_STR 72
#define SC_STR 108
#define QROWS 112
#define VROWS 104
#define SROWS 112
#define ATT_FLOATS (QROWS * QS_STR + DEPTH_ * KT_STR + VROWS * VS_STR + SROWS * SC_STR)
#define ATT_SMEM (ATT_FLOATS * 4)

__global__ __launch_bounds__(256)
void attention_kernel(const float* __restrict__ QKV, float* __restrict__ ctx) {
    extern __shared__ float sm[];
    float* qs = sm;
    float* kt = qs + QROWS * QS_STR;
    float* vs = kt + DEPTH_ * KT_STR;
    float* sc = vs + VROWS * VS_STR;

    int bh = blockIdx.x;
    int b = bh / H_;
    int h = bh % H_;
    int tid = threadIdx.x;
    int lane = tid & 31, warp = tid >> 5;
    int g = lane >> 2, tg = lane & 3;

    for (int i = tid; i < ATT_FLOATS; i += 256) sm[i] = 0.f;
    __syncthreads();

    for (int i = tid; i < S_ * (DEPTH_ / 4); i += 256) {
        int s = i >> 4, e4 = (i & 15) * 4;
        size_t off = ((size_t)(b * S_ + s)) * N_QKV + h * DEPTH_ + e4;
        float4 q = *(const float4*)(QKV + off);
        float4 k = *(const float4*)(QKV + off + D_);
        float4 v = *(const float4*)(QKV + off + 2 * D_);
        qs[s * QS_STR + e4 + 0] = roundtf(q.x);
        qs[s * QS_STR + e4 + 1] = roundtf(q.y);
        qs[s * QS_STR + e4 + 2] = roundtf(q.z);
        qs[s * QS_STR + e4 + 3] = roundtf(q.w);
        kt[(e4 + 0) * KT_STR + s] = roundtf(k.x);
        kt[(e4 + 1) * KT_STR + s] = roundtf(k.y);
        kt[(e4 + 2) * KT_STR + s] = roundtf(k.z);
        kt[(e4 + 3) * KT_STR + s] = roundtf(k.w);
        float4 vr = make_float4(roundtf(v.x), roundtf(v.y), roundtf(v.z), roundtf(v.w));
        *(float4*)&vs[s * VS_STR + e4] = vr;
    }
    __syncthreads();

    if (warp < 7) {
        float acc[13][4];
#pragma unroll
        for (int ni = 0; ni < 13; ni++)
#pragma unroll
            for (int c = 0; c < 4; c++) acc[ni][c] = 0.f;
        const uint32_t* qsu = (const uint32_t*)qs;
        const uint32_t* ktu = (const uint32_t*)kt;
        int m = warp * 16 + g;
#pragma unroll
        for (int ks = 0; ks < 8; ks++) {
            int k0 = ks * 8;
            uint32_t a[4];
            a[0] = qsu[m * QS_STR + k0 + tg];
            a[1] = qsu[(m + 8) * QS_STR + k0 + tg];
            a[2] = qsu[m * QS_STR + k0 + tg + 4];
            a[3] = qsu[(m + 8) * QS_STR + k0 + tg + 4];
#pragma unroll
            for (int ni = 0; ni < 13; ni++) {
                uint32_t bf[2];
                bf[0] = ktu[(k0 + tg) * KT_STR + ni * 8 + g];
                bf[1] = ktu[(k0 + tg + 4) * KT_STR + ni * 8 + g];
                mma_tf32(acc[ni], a, bf);
            }
        }
        const float scale = 0.125f;
#pragma unroll
        for (int ni = 0; ni < 13; ni++)
#pragma unroll
            for (int rr = 0; rr < 2; rr++) {
                int row = warp * 16 + rr * 8 + g;
                int col = ni * 8 + tg * 2;
                *(float2*)&sc[row * SC_STR + col] =
                    make_float2(acc[ni][rr * 2] * scale, acc[ni][rr * 2 + 1] * scale);
            }
    }
    __syncthreads();

    for (int r = warp; r < S_; r += 8) {
        float v0 = (lane < S_) ? sc[r * SC_STR + lane] : -1e30f;
        float v1 = sc[r * SC_STR + lane + 32];
        float v2 = (lane + 64 < S_) ? sc[r * SC_STR + lane + 64] : -1e30f;
        float v3 = (lane + 96 < S_) ? sc[r * SC_STR + lane + 96] : -1e30f;
        float m = fmaxf(fmaxf(v0, v1), fmaxf(v2, v3));
#pragma unroll
        for (int off = 16; off > 0; off >>= 1)
            m = fmaxf(m, __shfl_xor_sync(0xffffffffu, m, off));
        float e0 = (lane < S_) ? __expf(v0 - m) : 0.f;
        float e1 = __expf(v1 - m);
        float e2 = (lane + 64 < S_) ? __expf(v2 - m) : 0.f;
        float e3 = (lane + 96 < S_) ? __expf(v3 - m) : 0.f;
        float s = e0 + e1 + e2 + e3;
#pragma unroll
        for (int off = 16; off > 0; off >>= 1)
            s += __shfl_xor_sync(0xffffffffu, s, off);
        float inv = 1.f / s;
        if (lane < S_) sc[r * SC_STR + lane] = roundtf(e0 * inv);
        sc[r * SC_STR + lane + 32] = roundtf(e1 * inv);
        if (lane + 64 < S_) sc[r * SC_STR + lane + 64] = roundtf(e2 * inv);
        if (lane + 96 < S_) sc[r * SC_STR + lane + 96] = roundtf(e3 * inv);
    }
    __syncthreads();

    if (warp < 7) {
        float acc[8][4];
#pragma unroll
        for (int ni = 0; ni < 8; ni++)
#pragma unroll
            for (int c = 0; c < 4; c++) acc[ni][c] = 0.f;
        const uint32_t* scu = (const uint32_t*)sc;
        const uint32_t* vsu = (const uint32_t*)vs;
        int m = warp * 16 + g;
#pragma unroll
        for (int ks = 0; ks < 13; ks++) {
            int k0 = ks * 8;
            uint32_t a[4];
            a[0] = scu[m * SC_STR + k0 + tg];
            a[1] = scu[(m + 8) * SC_STR + k0 + tg];
            a[2] = scu[m * SC_STR + k0 + tg + 4];
            a[3] = scu[(m + 8) * SC_STR + k0 + tg + 4];
#pragma unroll
            for (int ni = 0; ni < 8; ni++) {
                uint32_t bf[2];
                bf[0] = vsu[(k0 + tg) * VS_STR + ni * 8 + g];
                bf[1] = vsu[(k0 + tg + 4) * VS_STR + ni * 8 + g];
                mma_tf32(acc[ni], a, bf);
            }
        }
        const size_t cbase = (size_t)b * S_ * D_ + (size_t)h * DEPTH_;
#pragma unroll
        for (int ni = 0; ni < 8; ni++)
#pragma unroll
            for (int rr = 0; rr < 2; rr++) {
                int row = warp * 16 + rr * 8 + g;
                if (row < S_) {
                    int col = ni * 8 + tg * 2;
                    *(float2*)&ctx[cbase + (size_t)row * D_ + col] =
                        make_float2(roundtf(acc[ni][rr * 2]), roundtf(acc[ni][rr * 2 + 1]));
                }
            }
    }
}

// ---------------------------------------------------------------------------
// Fused split-K reduce + bias + residual + LayerNorm.
// ---------------------------------------------------------------------------
template <bool ROUND2>
__global__ __launch_bounds__(256)
void lnred_kernel(const float* __restrict__ p0, const float* __restrict__ p1,
                  const float* __restrict__ bias, const float* __restrict__ res,
                  const float* __restrict__ gamma, const float* __restrict__ beta,
                  float* __restrict__ out, float* __restrict__ out_r) {
    int row = blockIdx.x;
    size_t base = (size_t)row * D_;
    int tid = threadIdx.x;

    float vals[4];
    float sum = 0.f, sq = 0.f;
#pragma unroll
    for (int r = 0; r < 4; r++) {
        int d = tid + r * 256;
        float v = p0[base + d] + p1[base + d] + bias[d] + res[base + d];
        vals[r] = v;
        sum += v;
        sq += v * v;
    }
#pragma unroll
    for (int off = 16; off > 0; off >>= 1) {
        sum += __shfl_xor_sync(0xffffffffu, sum, off);
        sq += __shfl_xor_sync(0xffffffffu, sq, off);
    }
    __shared__ float s1[8], s2[8];
    int wid = tid >> 5, lid = tid & 31;
    if (lid == 0) { s1[wid] = sum; s2[wid] = sq; }
    __syncthreads();
    if (wid == 0) {
        sum = (lid < 8) ? s1[lid] : 0.f;
        sq = (lid < 8) ? s2[lid] : 0.f;
#pragma unroll
        for (int off = 4; off > 0; off >>= 1) {
            sum += __shfl_xor_sync(0xffffffffu, sum, off);
            sq += __shfl_xor_sync(0xffffffffu, sq, off);
        }
        if (lid == 0) { s1[0] = sum; s2[0] = sq; }
    }
    __syncthreads();
    float mean = s1[0] * (1.0f / D_);
    float var = s2[0] * (1.0f / D_) - mean * mean;
    float inv = rsqrtf(var + EPS_);
#pragma unroll
    for (int r = 0; r < 4; r++) {
        int d = tid + r * 256;
        float o = gamma[d] * ((vals[r] - mean) * inv) + beta[d];
        out[base + d] = o;
        if (ROUND2) out_r[base + d] = roundtf(o);
    }
}

// ---------------------------------------------------------------------------
// Launch
// ---------------------------------------------------------------------------
extern "C" void kernel_launch(void* const* d_in, const int* in_sizes, int n_in,
                              void* d_out, int out_size) {
    const int* tokens = (const int*)d_in[0];
    const float* emb = (const float*)d_in[1];
    const float* Wq = (const float*)d_in[2];
    const float* bq = (const float*)d_in[3];
    const float* Wk = (const float*)d_in[4];
    const float* bk = (const float*)d_in[5];
    const float* Wv = (const float*)d_in[6];
    const float* bv = (const float*)d_in[7];
    const float* Wo = (const float*)d_in[8];
    const float* bo = (const float*)d_in[9];
    const float* W1 = (const float*)d_in[10];
    const float* b1 = (const float*)d_in[11];
    const float* W2 = (const float*)d_in[12];
    const float* b2 = (const float*)d_in[13];
    const float* gamma1 = (const float*)d_in[14];
    const float* beta1 = (const float*)d_in[15];
    const float* gamma2 = (const float*)d_in[16];
    const float* beta2 = (const float*)d_in[17];
    float* out = (float*)d_out;

    float *pe, *x, *xr, *Wqkv, *bqkv, *Wor, *W1r, *W2r, *QKV, *ctx, *t1, *x1, *x1r, *ffh;
    cudaGetSymbolAddress((void**)&pe, g_pe);
    cudaGetSymbolAddress((void**)&x, g_x);
    cudaGetSymbolAddress((void**)&xr, g_xr);
    cudaGetSymbolAddress((void**)&Wqkv, g_Wqkv);
    cudaGetSymbolAddress((void**)&bqkv, g_bqkv);
    cudaGetSymbolAddress((void**)&Wor, g_Wor);
    cudaGetSymbolAddress((void**)&W1r, g_W1r);
    cudaGetSymbolAddress((void**)&W2r, g_W2r);
    cudaGetSymbolAddress((void**)&QKV, g_QKV);
    cudaGetSymbolAddress((void**)&ctx, g_ctx);
    cudaGetSymbolAddress((void**)&t1, g_t1);
    cudaGetSymbolAddress((void**)&x1, g_x1);
    cudaGetSymbolAddress((void**)&x1r, g_x1r);
    cudaGetSymbolAddress((void**)&ffh, g_ffh);

    cudaFuncSetAttribute(attention_kernel,
                         cudaFuncAttributeMaxDynamicSharedMemorySize, ATT_SMEM);
    cudaFuncSetAttribute(mma_gemm<0>,
                         cudaFuncAttributeMaxDynamicSharedMemorySize, SMEM_GEMM);
    cudaFuncSetAttribute(mma_gemm<1>,
                         cudaFuncAttributeMaxDynamicSharedMemorySize, SMEM_GEMM);
    cudaFuncSetAttribute(mma_gemm<11>,
                         cudaFuncAttributeMaxDynamicSharedMemorySize, SMEM_GEMM);

    // 1. positional encoding + embedding (+ rounded twin)
    pe_kernel<<<(S_ * D_ + 255) / 256, 256>>>(pe);
    embed_kernel<<<(BS_ * D_ / 4 + 255) / 256, 256>>>(tokens, emb, pe, x, xr);

    // 2. weight prep
    permute_qkv_kernel<<<(3 * D_ * D_ + 255) / 256, 256>>>(Wq, Wk, Wv, bq, bk, bv,
                                                           Wqkv, bqkv);
    roundcpy3_kernel<<<(N4_WO + N4_W1 + N4_W2 + 255) / 256, 256>>>(Wo, Wor, W1, W1r,
                                                                   W2, W2r);

    // 3. fused QKV projection
    mma_gemm<1><<<dim3(N_QKV / 128, BS_ / 128), 128, SMEM_GEMM>>>(
        xr, Wqkv, QKV, bqkv, nullptr, BS_, N_QKV, D_);

    // 4. attention (tensor-core QK + AV; rounds ctx)
    attention_kernel<<<B_ * H_, 256, ATT_SMEM>>>(QKV, ctx);

    // 5. output projection (split-K 2, raw partials) + fused reduce+LN1
    mma_gemm<0><<<dim3(D_ / 128, BS_ / 128, 2), 128, SMEM_GEMM>>>(
        ctx, Wor, t1, nullptr, nullptr, BS_, D_, D_);
    lnred_kernel<true><<<BS_, 256>>>(t1, t1 + (size_t)BS_ * D_, bo, x,
                                     gamma1, beta1, x1, x1r);

    // 6. FFN: W1 (bias+relu+round epilogue), W2 (split-K 2, raw partials)
    mma_gemm<11><<<dim3(F_ / 128, BS_ / 128), 128, SMEM_GEMM>>>(
        x1r, W1r, ffh, b1, nullptr, BS_, F_, D_);
    mma_gemm<0><<<dim3(D_ / 128, BS_ / 128, 2), 128, SMEM_GEMM>>>(
        ffh, W2r, t1, nullptr, nullptr, BS_, D_, F_);

    // 7. fused reduce + LN2 -> output
    lnred_kernel<false><<<BS_, 256>>>(t1, t1 + (size_t)BS_ * D_, b2, x1,
                                      gamma2, beta2, out, nullptr);
}